// round 12
// baseline (speedup 1.0000x reference)
#include <cuda_runtime.h>
#include <cuda_bf16.h>

#define BB 8
#define LL 4096
#define DD 1024
#define CC 128
#define WIN 32
#define NW (LL / WIN)            // 128 windows per batch
#define NWTOT (BB * NW)          // 1024 window blocks

// Scan-published metadata
__device__ int4 g_chunk[BB][CC];      // {cnt, s, e, 0}
__device__ int  g_base[BB][NW];       // #boundaries in [0, w*WIN)
__device__ int  g_arrive[BB][CC];     // per-chunk arrival counters (reset by scan)
__device__ int  g_ready[BB];          // per-batch ready flags (self-cleaning)
__device__ int  g_fin;                // window completion counter (self-cleaning)

// Window edge pieces: 2 * 4 MB
__device__ float4 g_head[BB][NW][DD / 4];
__device__ float4 g_tail[BB][NW][DD / 4];

// --- memory-model helpers ---
__device__ __forceinline__ int atomic_add_acq_rel(int* p, int v) {
    int old;
    asm volatile("atom.add.acq_rel.gpu.s32 %0, [%1], %2;"
                 : "=r"(old) : "l"(p), "r"(v) : "memory");
    return old;
}
__device__ __forceinline__ void st_release(int* p, int v) {
    asm volatile("st.release.gpu.s32 [%0], %1;" :: "l"(p), "r"(v) : "memory");
}
__device__ __forceinline__ int ld_acquire(const int* p) {
    int v;
    asm volatile("ld.acquire.gpu.s32 %0, [%1];" : "=r"(v) : "l"(p) : "memory");
    return v;
}
__device__ __forceinline__ void f4add(float4& a, const float4& v) {
    a.x += v.x; a.y += v.y; a.z += v.z; a.w += v.w;
}

// Cold path: split-window corrections. Re-reads [0, p_last) from L2 (lines just
// loaded by the blind pass), produces head + interior means; tail = blind - sum.
__device__ __noinline__ void correct_window(
        const float4* __restrict__ xp, unsigned mi, int f0, int base,
        int b, int w, int t, float4 blind, float* __restrict__ means) {
    float4 sp = make_float4(0.f, 0.f, 0.f, 0.f);   // sum of pieces so far
    int ps = 0, pidx = 0;
    unsigned rem = mi;
    while (rem) {
        const int pe = __ffs(rem) - 1;
        rem &= rem - 1;
        float4 a = make_float4(0.f, 0.f, 0.f, 0.f);
#pragma unroll 4
        for (int i = ps; i < pe; i++) { float4 v = xp[i * 256]; f4add(a, v); }
        if (pidx == 0) {
            g_head[b][w][t] = a;                   // head piece
        } else {
            const int c = base - 1 + f0 + pidx;    // complete interior chunk
            if (c >= 0 && c < CC) {
                const float inv = 1.0f / (float)(pe - ps);
                float4 m = make_float4(a.x * inv, a.y * inv, a.z * inv, a.w * inv);
                reinterpret_cast<float4*>(means + ((size_t)b * CC + c) * DD)[t] = m;
            }
        }
        f4add(sp, a);
        ps = pe; pidx++;
    }
    // tail = blind - sum(pieces): deterministic, fp deviation ~1e-6 << 1e-3
    float4 tl = make_float4(blind.x - sp.x, blind.y - sp.y,
                            blind.z - sp.z, blind.w - sp.w);
    g_tail[b][w][t] = tl;
}

// deterministic fixed-window-order finalize
__device__ __noinline__ void finalize_chunk(int b, int c, int t,
                                            float* __restrict__ means) {
    const int4 mt = g_chunk[b][c];       // {cnt, s, e, 0}
    const int w0 = mt.y >> 5, w1 = (mt.z - 1) >> 5;
    float4 a = make_float4(0.f, 0.f, 0.f, 0.f);
    for (int ww = w0; ww <= w1; ww++) {
        float4 v = (((ww + 1) << 5) <= mt.z) ? g_tail[b][ww][t]
                                             : g_head[b][ww][t];
        f4add(a, v);
    }
    const float inv = 1.0f / (float)mt.x;
    a.x *= inv; a.y *= inv; a.z *= inv; a.w *= inv;
    reinterpret_cast<float4*>(means + ((size_t)b * CC + c) * DD)[t] = a;
}

// number of window blocks contributing edge pieces to chunk [s, e)
__device__ __forceinline__ int chunk_target(int s, int e) {
    const int w0 = s >> 5, w1 = (e - 1) >> 5;
    if (w1 > w0) return w1 - w0 + 1;
    return (((s & 31) == 0) || ((e & 31) == 0)) ? 1 : 0;
}

// ---------------------------------------------------------------------------
// One kernel, 8 + 1024 blocks (single wave at 7 CTAs/SM), 256 threads.
// ---------------------------------------------------------------------------
__global__ void __launch_bounds__(256, 7) chunk_blind_kernel(
        const float* __restrict__ x,
        const float* __restrict__ boundaries,
        float* __restrict__ means,
        float* __restrict__ cnts_out,
        int write_cnts) {
    const int t    = threadIdx.x;
    const int lane = t & 31;
    const int wid  = t >> 5;

    if (blockIdx.x < BB) {
        // ====================== SCAN BLOCK ======================
        const int b = blockIdx.x;
        __shared__ int wsum[8], wexcl[8], pos[CC + 1], snb, elist[CC], s_ne;
        if (t == 0) s_ne = 0;

        const float* bp = boundaries + (size_t)b * LL;
        const int base16 = t * 16;
        unsigned flags = 0;
        {
            const float4* bp4 = reinterpret_cast<const float4*>(bp + base16);
#pragma unroll
            for (int q = 0; q < 4; q++) {
                float4 v = bp4[q];
                if (v.x > 0.5f) flags |= 1u << (q * 4 + 0);
                if (v.y > 0.5f) flags |= 1u << (q * 4 + 1);
                if (v.z > 0.5f) flags |= 1u << (q * 4 + 2);
                if (v.w > 0.5f) flags |= 1u << (q * 4 + 3);
            }
        }
        const int cnt = __popc(flags);

        int incl = cnt;
#pragma unroll
        for (int d = 1; d < 32; d <<= 1) {
            int v = __shfl_up_sync(0xFFFFFFFFu, incl, d);
            if (lane >= d) incl += v;
        }
        if (lane == 31) wsum[wid] = incl;
        __syncthreads();

        if (t < 8) {
            int v = wsum[t];
            int iv = v;
#pragma unroll
            for (int d = 1; d < 8; d <<= 1) {
                int u = __shfl_up_sync(0x000000FFu, iv, d);
                if (t >= d) iv += u;
            }
            wexcl[t] = iv - v;
            if (t == 7) snb = iv;
        }
        __syncthreads();

        const int excl = wexcl[wid] + (incl - cnt);   // boundaries before token base16
        if ((t & 1) == 0) g_base[b][t >> 1] = excl;   // 2 threads * 16 tok = WIN

        {
            int idx = excl;
            unsigned f = flags;
            while (f) {
                int i = __ffs(f) - 1;
                f &= f - 1;
                if (idx <= CC) pos[idx] = base16 + i;
                idx++;
            }
        }
        __syncthreads();

        const int nb = snb;
        const int valid = nb < CC ? nb : CC;

        if (t < CC) {
            int len = 0, s0 = 0, e0 = 0;
            if (t < valid) {
                s0 = pos[t];
                e0 = (t + 1 < nb) ? pos[t + 1] : LL;
                len = e0 - s0;
            }
            g_chunk[b][t]  = make_int4(len, s0, e0, 0);
            g_arrive[b][t] = 0;
            if (len == 0) elist[atomicAdd(&s_ne, 1)] = t;
        }
        __syncthreads();

        if (t == 0) st_release(&g_ready[b], 1);   // publish EARLY

        // post-release housekeeping
        const int ne = s_ne;
        const float4 z = make_float4(0.f, 0.f, 0.f, 0.f);
        for (int i = 0; i < ne; i++) {
            reinterpret_cast<float4*>(
                means + ((size_t)b * CC + elist[i]) * DD)[t] = z;
        }
        if (write_cnts && t < CC) cnts_out[b * CC + t] = (float)g_chunk[b][t].x;
        return;
    }

    // ====================== WINDOW BLOCK ======================
    const int gw = blockIdx.x - BB;
    const int b  = gw >> 7;             // / NW
    const int w  = gw & (NW - 1);

    __shared__ int s_base, s_c0, s_c1;

    // 1. boundary mask (one 128B warp-broadcast load; identical in all warps)
    const float* bpt = boundaries + (size_t)b * LL + w * WIN;
    const unsigned m  = __ballot_sync(0xFFFFFFFFu, bpt[lane] > 0.5f);
    const int f0      = (int)(m & 1u);
    const unsigned mi = m & ~1u;        // in-window splits (j > 0)

    // 2. blind full-window sum: static addresses, branch-free, issues at cycle 0
    const float4* __restrict__ xp =
        reinterpret_cast<const float4*>(x) + (b * LL + w * WIN) * (DD / 4) + t;

    float4 a0 = make_float4(0.f, 0.f, 0.f, 0.f);
    float4 a1 = make_float4(0.f, 0.f, 0.f, 0.f);
#pragma unroll
    for (int i = 0; i < WIN; i += 2) {
        float4 v0 = xp[(i + 0) * 256];
        float4 v1 = xp[(i + 1) * 256];
        f4add(a0, v0);
        f4add(a1, v1);
    }
    f4add(a0, a1);                      // blind = a0

    // 3. spin (scan long done by now) + distribute base
    if (t == 0) {
        while (ld_acquire(&g_ready[b]) == 0) __nanosleep(32);
        s_base = g_base[b][w];
    }
    __syncthreads();
    const int base = s_base;

    // 4. publish pieces
    if (mi == 0) {
        g_tail[b][w][t] = a0;           // whole window is one piece
    } else {
        correct_window(xp, mi, f0, base, b, w, t, a0, means);
    }
    __syncthreads();                    // all edge stores complete

    // 5. arrival bumps + unique deterministic finalize
    if (t == 0) {
        int c0 = -1, c1 = -1;
        const int ct = base + __popc(m) - 1;        // tail piece's chunk
        if (ct >= 0 && ct < CC) {
            const int4 mt = g_chunk[b][ct];
            if (atomic_add_acq_rel(&g_arrive[b][ct], 1) + 1 ==
                chunk_target(mt.y, mt.z)) c0 = ct;
        }
        if (mi != 0u) {                             // separate head piece
            const int ch = base - 1 + f0;
            if (ch >= 0 && ch < CC) {
                const int4 mt = g_chunk[b][ch];
                if (atomic_add_acq_rel(&g_arrive[b][ch], 1) + 1 ==
                    chunk_target(mt.y, mt.z)) c1 = ch;
            }
        }
        s_c0 = c0; s_c1 = c1;
    }
    __syncthreads();

    if (s_c0 >= 0) finalize_chunk(b, s_c0, t, means);
    if (s_c1 >= 0) finalize_chunk(b, s_c1, t, means);

    // self-cleaning for graph replay
    if (t == 0) {
        if (atomic_add_acq_rel(&g_fin, 1) == NWTOT - 1) {
#pragma unroll
            for (int i = 0; i < BB; i++) g_ready[i] = 0;
            g_fin = 0;
        }
    }
}

extern "C" void kernel_launch(void* const* d_in, const int* in_sizes, int n_in,
                              void* d_out, int out_size) {
    const float* x = nullptr;
    const float* boundaries = nullptr;
    for (int i = 0; i < n_in; i++) {
        if (in_sizes[i] == BB * LL * DD) x = (const float*)d_in[i];
        else if (in_sizes[i] == BB * LL) boundaries = (const float*)d_in[i];
    }

    float* out = (float*)d_out;
    const int means_elems = BB * CC * DD;
    const int write_cnts = (out_size > means_elems) ? 1 : 0;

    chunk_blind_kernel<<<BB + NWTOT, 256>>>(
        x, boundaries, out, out + means_elems, write_cnts);
}

// round 13
// speedup vs baseline: 1.1272x; 1.1272x over previous
#include <cuda_runtime.h>
#include <cuda_bf16.h>

#define BB 8
#define LL 4096
#define DD 1024
#define CC 128
#define SLICE 32
#define MAXSL 256                 // slice slots per batch (>= L/32 + C guaranteed)

// Only cross-block state: arrival counters (zero-init; finalizer self-cleans)
// and the partial-sum scratch.
__device__ int    g_arrive[BB][CC];
__device__ float4 g_part[BB][MAXSL][DD / 4];   // 8 MB

__device__ __forceinline__ int atomic_add_acq_rel(int* p, int v) {
    int old;
    asm volatile("atom.add.acq_rel.gpu.s32 %0, [%1], %2;"
                 : "=r"(old) : "l"(p), "r"(v) : "memory");
    return old;
}

// Cold path: deterministic fixed-order reduction of a chunk's slice partials.
__device__ __noinline__ void finalize_multi(int b, int c, int t,
                                            int first_sl, int nsl, int cnt,
                                            float4* __restrict__ mp) {
    float4 acc = make_float4(0.f, 0.f, 0.f, 0.f);
    for (int i = 0; i < nsl; i++) {
        float4 v = g_part[b][first_sl + i][t];
        acc.x += v.x; acc.y += v.y; acc.z += v.z; acc.w += v.w;
    }
    const float inv = 1.0f / (float)cnt;
    acc.x *= inv; acc.y *= inv; acc.z *= inv; acc.w *= inv;
    mp[t] = acc;
}

// ---------------------------------------------------------------------------
// Single kernel, grid = BB*MAXSL = 2048 blocks, 256 threads.
// Block (b, sl): redundantly computes the per-batch scan from boundaries
// (16 KB, L2-hot), derives its OWN slice, streams it, finalizes via arrival
// counters. sl >= nsl_total blocks zero the empty/invalid chunks. No
// cross-block waiting anywhere.
// ---------------------------------------------------------------------------
__global__ void __launch_bounds__(256) chunk_selfscan_kernel(
        const float* __restrict__ x,
        const float* __restrict__ boundaries,
        float* __restrict__ means,
        float* __restrict__ cnts_out,
        int write_cnts) {
    const int t    = threadIdx.x;       // 0..255
    const int lane = t & 31;
    const int wid  = t >> 5;            // 0..7
    const int b    = blockIdx.x >> 8;   // / MAXSL
    const int sl   = blockIdx.x & (MAXSL - 1);

    __shared__ int wsum[8], wexcl[8], pos[CC + 1], snb;
    __shared__ int csum[4], cexcl[4], snsl;
    __shared__ int s_meta[6];           // {s, e, chunk, first_sl, nsl, cnt}
    __shared__ int s_last;

    // ---- phase 1: boundary flags (16 tokens/thread) + ordered compaction ----
    const float* bp = boundaries + (size_t)b * LL;
    const int base = t * 16;
    unsigned flags = 0;
    {
        const float4* bp4 = reinterpret_cast<const float4*>(bp + base);
#pragma unroll
        for (int q = 0; q < 4; q++) {
            float4 v = bp4[q];
            if (v.x > 0.5f) flags |= 1u << (q * 4 + 0);
            if (v.y > 0.5f) flags |= 1u << (q * 4 + 1);
            if (v.z > 0.5f) flags |= 1u << (q * 4 + 2);
            if (v.w > 0.5f) flags |= 1u << (q * 4 + 3);
        }
    }
    const int cnt_t = __popc(flags);

    int incl = cnt_t;
#pragma unroll
    for (int d = 1; d < 32; d <<= 1) {
        int v = __shfl_up_sync(0xFFFFFFFFu, incl, d);
        if (lane >= d) incl += v;
    }
    if (lane == 31) wsum[wid] = incl;
    __syncthreads();

    if (t < 8) {
        int v = wsum[t];
        int iv = v;
#pragma unroll
        for (int d = 1; d < 8; d <<= 1) {
            int u = __shfl_up_sync(0x000000FFu, iv, d);
            if (t >= d) iv += u;
        }
        wexcl[t] = iv - v;
        if (t == 7) snb = iv;
    }
    __syncthreads();

    {
        int idx = wexcl[wid] + (incl - cnt_t);
        unsigned f = flags;
        while (f) {
            int i = __ffs(f) - 1;
            f &= f - 1;
            if (idx <= CC) pos[idx] = base + i;
            idx++;
        }
    }
    __syncthreads();

    const int nb = snb;
    const int valid = nb < CC ? nb : CC;

    // ---- phase 2: chunk ranges + slice-count prefix; locate OUR slice ----
    int s0 = 0, e0 = 0, len = 0, nsl = 0;
    if (t < CC && t < valid) {
        s0 = pos[t];
        e0 = (t + 1 < nb) ? pos[t + 1] : LL;
        len = e0 - s0;
        nsl = (len + SLICE - 1) / SLICE;
    }

    int cincl = nsl;
#pragma unroll
    for (int d = 1; d < 32; d <<= 1) {
        int v = __shfl_up_sync(0xFFFFFFFFu, cincl, d);
        if (lane >= d) cincl += v;
    }
    if (t < CC && lane == 31) csum[wid] = cincl;
    __syncthreads();

    if (t < 4) {
        int v = csum[t];
        int iv = v;
#pragma unroll
        for (int d = 1; d < 4; d <<= 1) {
            int u = __shfl_up_sync(0x0000000Fu, iv, d);
            if (t >= d) iv += u;
        }
        cexcl[t] = iv - v;
        if (t == 3) snsl = iv;
    }
    __syncthreads();

    const int nsl_total = snsl;

    if (t < CC && t < valid) {
        const int soff = cexcl[wid] + (cincl - nsl);
        if (soff <= sl && sl < soff + nsl) {      // exactly one thread matches
            const int ss = s0 + (sl - soff) * SLICE;
            const int ee = (ss + SLICE) < e0 ? (ss + SLICE) : e0;
            s_meta[0] = ss; s_meta[1] = ee; s_meta[2] = t;
            s_meta[3] = soff; s_meta[4] = nsl; s_meta[5] = len;
        }
    }
    // cnts output: one designated block per batch (before the branch so it
    // also runs when nsl_total == 0)
    if (write_cnts && sl == 0 && t < CC) {
        cnts_out[b * CC + t] = (float)len;        // len==0 for t >= valid
    }
    __syncthreads();

    // ---- idle slice slots take zeroing duty for empty/invalid chunks ----
    if (sl >= nsl_total) {
        const int c = valid + (sl - nsl_total);   // empty chunks are [valid, CC)
        if (c < CC) {
            const float4 z = make_float4(0.f, 0.f, 0.f, 0.f);
            reinterpret_cast<float4*>(
                means + ((size_t)b * CC + c) * DD)[t] = z;
        }
        return;
    }

    // ---- stream our slice (round-10 validated loop) ----
    const int ss     = s_meta[0];
    const int ee     = s_meta[1];
    const int c      = s_meta[2];
    const int first  = s_meta[3];
    const int nsl_c  = s_meta[4];
    const int cnt_c  = s_meta[5];
    const int n      = ee - ss;

    // 32-bit offset math (fits: 8*4096*1024 < 2^31)
    const float4* __restrict__ xp =
        reinterpret_cast<const float4*>(x) + (b * LL + ss) * (DD / 4) + t;

    float4 a0 = make_float4(0.f, 0.f, 0.f, 0.f);
    float4 a1 = make_float4(0.f, 0.f, 0.f, 0.f);

    if (n == SLICE) {
#pragma unroll
        for (int i = 0; i < SLICE; i += 2) {
            float4 v0 = xp[(i + 0) * (DD / 4)];
            float4 v1 = xp[(i + 1) * (DD / 4)];
            a0.x += v0.x; a0.y += v0.y; a0.z += v0.z; a0.w += v0.w;
            a1.x += v1.x; a1.y += v1.y; a1.z += v1.z; a1.w += v1.w;
        }
    } else {
        int i = 0;
#pragma unroll 4
        for (; i + 1 < n; i += 2) {
            float4 v0 = xp[(i + 0) * (DD / 4)];
            float4 v1 = xp[(i + 1) * (DD / 4)];
            a0.x += v0.x; a0.y += v0.y; a0.z += v0.z; a0.w += v0.w;
            a1.x += v1.x; a1.y += v1.y; a1.z += v1.z; a1.w += v1.w;
        }
        if (i < n) {
            float4 v0 = xp[i * (DD / 4)];
            a0.x += v0.x; a0.y += v0.y; a0.z += v0.z; a0.w += v0.w;
        }
    }
    a0.x += a1.x; a0.y += a1.y; a0.z += a1.z; a0.w += a1.w;

    float4* __restrict__ mp =
        reinterpret_cast<float4*>(means + ((size_t)b * CC + c) * DD);

    if (nsl_c == 1) {
        const float inv = 1.0f / (float)n;
        a0.x *= inv; a0.y *= inv; a0.z *= inv; a0.w *= inv;
        mp[t] = a0;
        return;
    }

    // multi-slice: publish partial, last-arriving block finalizes (fixed order)
    g_part[b][sl][t] = a0;
    __syncthreads();                  // all partial stores before t0's release
    if (t == 0) {
        s_last = (atomic_add_acq_rel(&g_arrive[b][c], 1) == nsl_c - 1);
    }
    __syncthreads();                  // distribute acquire
    if (s_last) {
        finalize_multi(b, c, t, first, nsl_c, cnt_c, mp);
        if (t == 0) g_arrive[b][c] = 0;   // self-clean for graph replay
    }
}

extern "C" void kernel_launch(void* const* d_in, const int* in_sizes, int n_in,
                              void* d_out, int out_size) {
    const float* x = nullptr;
    const float* boundaries = nullptr;
    for (int i = 0; i < n_in; i++) {
        if (in_sizes[i] == BB * LL * DD) x = (const float*)d_in[i];
        else if (in_sizes[i] == BB * LL) boundaries = (const float*)d_in[i];
    }

    float* out = (float*)d_out;
    const int means_elems = BB * CC * DD;
    const int write_cnts = (out_size > means_elems) ? 1 : 0;

    chunk_selfscan_kernel<<<BB * MAXSL, 256>>>(
        x, boundaries, out, out + means_elems, write_cnts);
}